// round 7
// baseline (speedup 1.0000x reference)
#include <cuda_runtime.h>

#define B 8
#define T 1024
#define E 128
#define H 8
#define S 16
#define BH (B*H)

typedef unsigned long long ull;
__device__ __forceinline__ ull ffma2(ull a, ull b, ull c) {
    ull d; asm("fma.rn.f32x2 %0, %1, %2, %3;" : "=l"(d) : "l"(a), "l"(b), "l"(c)); return d;
}
__device__ __forceinline__ ull fmul2(ull a, ull b) {
    ull d; asm("mul.rn.f32x2 %0, %1, %2;" : "=l"(d) : "l"(a), "l"(b)); return d;
}
__device__ __forceinline__ ull fadd2(ull a, ull b) {
    ull d; asm("add.rn.f32x2 %0, %1, %2;" : "=l"(d) : "l"(a), "l"(b)); return d;
}
__device__ __forceinline__ ull pack2(float lo, float hi) {
    ull d; asm("mov.b64 %0, {%1, %2};" : "=l"(d) : "f"(lo), "f"(hi)); return d;
}
__device__ __forceinline__ void unpack2(ull a, float& lo, float& hi) {
    asm("mov.b64 {%0, %1}, %2;" : "=f"(lo), "=f"(hi) : "l"(a));
}

// ---- scratch ----
__device__ float g_Qt[BH*S*T];     // Q transposed: [bh][d][rank]
__device__ float g_Kt[BH*S*T];     // K transposed: [bh][d][rank]
__device__ float g_Vc[BH*T*S];     // V: [bh][rank][d]
__device__ float g_AttnO[B*T*E];   // attention output (pre-projection)
__device__ int   g_idx[B*T];       // compacted j -> original t
__device__ int   g_rank[B*T];      // original t -> compacted j (or -1)
__device__ int   g_cnt[B];         // unmasked count per batch

// ------------------------------------------------------------------
// 1. Order-preserving compaction of unmasked positions (per batch)
// ------------------------------------------------------------------
__global__ void compact_kernel(const int* __restrict__ masks) {
    int b = blockIdx.x;
    int t = threadIdx.x;            // 1024 threads
    int v = (masks[b*T + t] != 0) ? 1 : 0;
    unsigned bal = __ballot_sync(0xffffffffu, v);
    int lane = t & 31, warp = t >> 5;
    int wprefix = __popc(bal & ((1u << lane) - 1u));
    __shared__ int wcnt[32];
    __shared__ int wbase[32];
    if (lane == 31) wcnt[warp] = wprefix + v;
    __syncthreads();
    if (t == 0) {
        int acc = 0;
        for (int w = 0; w < 32; w++) { wbase[w] = acc; acc += wcnt[w]; }
        g_cnt[b] = acc;
    }
    __syncthreads();
    int r = v ? (wbase[warp] + wprefix) : -1;
    g_rank[b*T + t] = r;
    if (v) g_idx[b*T + r] = t;
}

// ------------------------------------------------------------------
// 2. QKV projection: writes Q,K d-major (transposed), V row-major.
//    Thread map: h slow, bt fast (coalesced transposed stores).
// ------------------------------------------------------------------
__global__ __launch_bounds__(256) void qkv_kernel(
    const float* __restrict__ x, const int* __restrict__ masks,
    const float* __restrict__ Wq, const float* __restrict__ Wk,
    const float* __restrict__ Wv)
{
    __shared__ float sW[3][S*S];
    int tid = threadIdx.x;
    sW[0][tid] = Wq[tid];
    sW[1][tid] = Wk[tid];
    sW[2][tid] = Wv[tid];
    __syncthreads();

    int gid = blockIdx.x * 256 + tid;   // h*(B*T) + bt
    int h  = gid >> 13;                 // B*T = 8192
    int bt = gid & 8191;
    int b  = bt >> 10;
    if (!masks[bt]) {
        float4 z = make_float4(0.f, 0.f, 0.f, 0.f);
        float4* op = (float4*)(g_AttnO + bt*E + h*S);
        op[0] = z; op[1] = z; op[2] = z; op[3] = z;
        return;
    }
    float xr[S];
    const float4* xp = (const float4*)(x + bt*E + h*S);
#pragma unroll
    for (int i = 0; i < 4; i++) {
        float4 v = xp[i];
        xr[4*i] = v.x; xr[4*i+1] = v.y; xr[4*i+2] = v.z; xr[4*i+3] = v.w;
    }
    int r  = g_rank[bt];
    int bh = b*H + h;
    const float invs = 0.29730177875068026f;   // 128^-0.25

    float o[S];
    // Q -> transposed
#pragma unroll
    for (int d = 0; d < S; d++) {
        float a = 0.f;
#pragma unroll
        for (int s2 = 0; s2 < S; s2++) a = fmaf(sW[0][d*S + s2], xr[s2], a);
        g_Qt[(bh*S + d)*T + r] = a * invs;
    }
    // K -> transposed
#pragma unroll
    for (int d = 0; d < S; d++) {
        float a = 0.f;
#pragma unroll
        for (int s2 = 0; s2 < S; s2++) a = fmaf(sW[1][d*S + s2], xr[s2], a);
        g_Kt[(bh*S + d)*T + r] = a * invs;
    }
    // V row-major
#pragma unroll
    for (int d = 0; d < S; d++) {
        float a = 0.f;
#pragma unroll
        for (int s2 = 0; s2 < S; s2++) a = fmaf(sW[2][d*S + s2], xr[s2], a);
        o[d] = a;
    }
    {
        float4* vp = (float4*)(g_Vc + (bh*T + r)*S);
#pragma unroll
        for (int i = 0; i < 4; i++) vp[i] = make_float4(o[4*i], o[4*i+1], o[4*i+2], o[4*i+3]);
    }
}

// ------------------------------------------------------------------
// 3. Tiled attention: per (bh, 128-query tile) block, loop key tiles.
//    Phase A: 128x128x16 GEMM -> exp -> smem P.  Phase B: P x V.
// ------------------------------------------------------------------
#define QT 128
#define KT 128
#define ATH 256
#define PPAD 129
// smem float offsets
#define OFF_QT   0                  // 16*128
#define OFF_KT   2048               // 16*128
#define OFF_VT   4096               // 128*16
#define OFF_P    6144               // 128*129 = 16512
#define SMEM_FLOATS (OFF_P + QT*PPAD)   // 22656
#define ATTN_SMEM_BYTES (SMEM_FLOATS*4) // 90624

__global__ __launch_bounds__(ATH, 2) void attn_kernel() {
    extern __shared__ float sm[];
    float* sQ = sm + OFF_QT;
    float* sK = sm + OFF_KT;
    float* sV = sm + OFF_VT;
    float* sP = sm + OFF_P;

    int bh = blockIdx.y;
    int b  = bh >> 3;
    int h  = bh & 7;
    int cnt = g_cnt[b];
    int q0 = blockIdx.x * QT;
    if (q0 >= cnt) return;
    int tid = threadIdx.x;

    // ---- load Q tile (d-major): 2048 floats ----
    {
        const float* gq = g_Qt + bh*S*T;
#pragma unroll
        for (int c = 0; c < 2; c++) {
            int f = tid + c*256;           // float4 index
            int d = f >> 5, col = (f & 31) * 4;
            *(float4*)&sQ[d*128 + col] = *(const float4*)&gq[d*T + q0 + col];
        }
    }

    // phase A thread map
    int tx = tid & 15, ty = tid >> 4;
    // phase B thread map
    int slot = tid & 63, kg = tid >> 6;
    int qs = slot & 31, ds = slot >> 5;

    ull ob[4][4];
    float lsum[4];
#pragma unroll
    for (int i = 0; i < 4; i++) {
        lsum[i] = 0.f;
#pragma unroll
        for (int m = 0; m < 4; m++) ob[i][m] = 0ULL;
    }

    const float* gk = g_Kt + bh*S*T;
    const float* gv = g_Vc + bh*T*S;

    for (int kt = 0; kt < cnt; kt += KT) {
        int nk = min(KT, cnt - kt);
        __syncthreads();
        // ---- load K (d-major) and V tiles ----
#pragma unroll
        for (int c = 0; c < 2; c++) {
            int f = tid + c*256;
            int d = f >> 5, col = (f & 31) * 4;
            *(float4*)&sK[d*128 + col] = *(const float4*)&gk[d*T + kt + col];
        }
#pragma unroll
        for (int c = 0; c < 2; c++) {
            int f = tid + c*256;
            int row = f >> 2, col = (f & 3) * 4;
            *(float4*)&sV[row*16 + col] = *(const float4*)&gv[(kt + row)*S + col];
        }
        __syncthreads();

        // ---- phase A: scores + exp -> sP (two key groups of 4) ----
#pragma unroll
        for (int g = 0; g < 2; g++) {
            ull acc[4][4];
#pragma unroll
            for (int i2 = 0; i2 < 4; i2++)
#pragma unroll
                for (int j = 0; j < 4; j++) acc[i2][j] = 0ULL;
#pragma unroll
            for (int d = 0; d < S; d++) {
                float4 qa = *(const float4*)&sQ[d*128 + ty*8];
                float4 qb = *(const float4*)&sQ[d*128 + ty*8 + 4];
                float4 ka = *(const float4*)&sK[d*128 + g*64 + tx*4];
                ull qp[4] = { pack2(qa.x, qa.y), pack2(qa.z, qa.w),
                              pack2(qb.x, qb.y), pack2(qb.z, qb.w) };
                float kf[4] = { ka.x, ka.y, ka.z, ka.w };
#pragma unroll
                for (int j = 0; j < 4; j++) {
                    ull k2 = pack2(kf[j], kf[j]);
#pragma unroll
                    for (int i2 = 0; i2 < 4; i2++)
                        acc[i2][j] = ffma2(qp[i2], k2, acc[i2][j]);
                }
            }
#pragma unroll
            for (int j = 0; j < 4; j++) {
                int kk = g*64 + tx*4 + j;
                bool kv = kk < nk;
#pragma unroll
                for (int i2 = 0; i2 < 4; i2++) {
                    float s0, s1; unpack2(acc[i2][j], s0, s1);
                    float w0 = kv ? __expf(s0) : 0.f;
                    float w1 = kv ? __expf(s1) : 0.f;
                    sP[(ty*8 + i2*2    )*PPAD + kk] = w0;
                    sP[(ty*8 + i2*2 + 1)*PPAD + kk] = w1;
                }
            }
        }
        __syncthreads();

        // ---- phase B: o += P * V over this tile's key quarter ----
        int kbase = kg * 32;
#pragma unroll 4
        for (int kk2 = 0; kk2 < 32; kk2++) {
            int k = kbase + kk2;
            float p0 = sP[(qs      )*PPAD + k];
            float p1 = sP[(qs +  32)*PPAD + k];
            float p2 = sP[(qs +  64)*PPAD + k];
            float p3 = sP[(qs +  96)*PPAD + k];
            const ull* vv = (const ull*)&sV[k*16 + ds*8];
            ull v0 = vv[0], v1 = vv[1], v2 = vv[2], v3 = vv[3];
            if (ds == 0) { lsum[0] += p0; lsum[1] += p1; lsum[2] += p2; lsum[3] += p3; }
            ull pp0 = pack2(p0, p0), pp1 = pack2(p1, p1);
            ull pp2 = pack2(p2, p2), pp3 = pack2(p3, p3);
            ob[0][0] = ffma2(pp0, v0, ob[0][0]); ob[0][1] = ffma2(pp0, v1, ob[0][1]);
            ob[0][2] = ffma2(pp0, v2, ob[0][2]); ob[0][3] = ffma2(pp0, v3, ob[0][3]);
            ob[1][0] = ffma2(pp1, v0, ob[1][0]); ob[1][1] = ffma2(pp1, v1, ob[1][1]);
            ob[1][2] = ffma2(pp1, v2, ob[1][2]); ob[1][3] = ffma2(pp1, v3, ob[1][3]);
            ob[2][0] = ffma2(pp2, v0, ob[2][0]); ob[2][1] = ffma2(pp2, v1, ob[2][1]);
            ob[2][2] = ffma2(pp2, v2, ob[2][2]); ob[2][3] = ffma2(pp2, v3, ob[2][3]);
            ob[3][0] = ffma2(pp3, v0, ob[3][0]); ob[3][1] = ffma2(pp3, v1, ob[3][1]);
            ob[3][2] = ffma2(pp3, v2, ob[3][2]); ob[3][3] = ffma2(pp3, v3, ob[3][3]);
        }
    }

    // ---- reduce the 4 key-group partials (reuse sP region) ----
    __syncthreads();
    ull*   red2 = (ull*)sP;            // 4096 ull = 8192 floats (fits in P)
    float* redl = sP + 8192;           // 512 floats
    float* linv = sm;                  // reuse Q tile area: 128 floats
#pragma unroll
    for (int i = 0; i < 4; i++)
#pragma unroll
        for (int m = 0; m < 4; m++)
            red2[(ds*4 + m)*512 + kg*128 + (qs + 32*i)] = ob[i][m];
    if (ds == 0) {
#pragma unroll
        for (int i = 0; i < 4; i++) redl[kg*128 + qs + 32*i] = lsum[i];
    }
    __syncthreads();
    if (tid < 64) {
#pragma unroll
        for (int i = 0; i < 4; i++) {
            int q = qs + 32*i;
#pragma unroll
            for (int m = 0; m < 4; m++) {
                ull a = ob[i][m];
                a = fadd2(a, red2[(ds*4 + m)*512 + 128 + q]);
                a = fadd2(a, red2[(ds*4 + m)*512 + 256 + q]);
                a = fadd2(a, red2[(ds*4 + m)*512 + 384 + q]);
                ob[i][m] = a;
            }
            if (ds == 0) {
                float L = lsum[i] + redl[128 + q] + redl[256 + q] + redl[384 + q];
                linv[q] = (L > 0.f) ? (1.0f / L) : 0.f;
            }
        }
    }
    __syncthreads();
    if (tid < 64) {
#pragma unroll
        for (int i = 0; i < 4; i++) {
            int q = qs + 32*i;
            int qg = q0 + q;
            if (qg < cnt) {
                float inv = linv[q];
                ull inv2 = pack2(inv, inv);
                int t = g_idx[b*T + qg];
                ull* op = (ull*)(g_AttnO + (b*T + t)*E + h*S + ds*8);
#pragma unroll
                for (int m = 0; m < 4; m++) op[m] = fmul2(ob[i][m], inv2);
            }
        }
    }
}

// ------------------------------------------------------------------
// 4. Output projection with in-block Wu transpose: out = AttnO @ Wu^T + bu
// ------------------------------------------------------------------
#define PR 32
#define WPAD 132
#define PROJ_SMEM_BYTES ((E*WPAD + PR*E)*4)   // 83968

__global__ __launch_bounds__(1024) void proj_kernel(
    const float* __restrict__ Wu, const float* __restrict__ bu,
    float* __restrict__ out)
{
    extern __shared__ float ps[];
    float* Ws = ps;              // [E][WPAD] transposed Wu
    float* xs = ps + E*WPAD;     // [PR][E]
    int tid = threadIdx.x;       // 1024
    int rowbase = blockIdx.x * PR;

    // transpose Wu into smem: Ws[c][r] = Wu[r][c]
#pragma unroll
    for (int c = 0; c < 4; c++) {
        int f = tid*4 + c;               // float4 index, 4096 total
        int r = f >> 5, cc = (f & 31) * 4;
        float4 w = *(const float4*)&Wu[r*E + cc];
        Ws[(cc+0)*WPAD + r] = w.x;
        Ws[(cc+1)*WPAD + r] = w.y;
        Ws[(cc+2)*WPAD + r] = w.z;
        Ws[(cc+3)*WPAD + r] = w.w;
    }
    // load x rows
    {
        int row = tid >> 5, col = (tid & 31) * 4;
        *(float4*)&xs[row*E + col] = *(const float4*)&g_AttnO[(rowbase + row)*E + col];
    }
    __syncthreads();

    int row = tid >> 5;           // 0..31 (warp-uniform)
    int cg  = (tid & 31) * 4;
    float ax = 0.f, ay = 0.f, az = 0.f, aw = 0.f;
#pragma unroll 8
    for (int i = 0; i < E; i++) {
        float xv = xs[row*E + i];
        float4 w = *(const float4*)&Ws[i*WPAD + cg];
        ax = fmaf(xv, w.x, ax); ay = fmaf(xv, w.y, ay);
        az = fmaf(xv, w.z, az); aw = fmaf(xv, w.w, aw);
    }
    float4 bb = *(const float4*)(bu + cg);
    *(float4*)(out + (rowbase + row)*E + cg) =
        make_float4(ax + bb.x, ay + bb.y, az + bb.z, aw + bb.w);
}

// ------------------------------------------------------------------
extern "C" void kernel_launch(void* const* d_in, const int* in_sizes, int n_in,
                              void* d_out, int out_size) {
    const float* x     = (const float*)d_in[0];
    const int*   masks = (const int*)  d_in[1];
    const float* Wq    = (const float*)d_in[2];
    const float* Wk    = (const float*)d_in[3];
    const float* Wv    = (const float*)d_in[4];
    const float* Wu    = (const float*)d_in[5];
    const float* bu    = (const float*)d_in[6];
    float* out = (float*)d_out;

    cudaFuncSetAttribute(attn_kernel, cudaFuncAttributeMaxDynamicSharedMemorySize, ATTN_SMEM_BYTES);
    cudaFuncSetAttribute(proj_kernel, cudaFuncAttributeMaxDynamicSharedMemorySize, PROJ_SMEM_BYTES);

    compact_kernel<<<B, 1024>>>(masks);
    qkv_kernel<<<(B*T*H)/256, 256>>>(x, masks, Wq, Wk, Wv);
    attn_kernel<<<dim3(T/QT, BH), ATH, ATTN_SMEM_BYTES>>>();
    proj_kernel<<<(B*T)/PR, 1024, PROJ_SMEM_BYTES>>>(Wu, bu, out);
}

// round 8
// speedup vs baseline: 2.1517x; 2.1517x over previous
#include <cuda_runtime.h>

#define B 8
#define T 1024
#define E 128
#define H 8
#define S 16
#define BH (B*H)
#define KSPLIT 8

// ---- packed f32x2 helpers (sm_103a FFMA2 path, PTX-only) ----
typedef unsigned long long ull;
__device__ __forceinline__ ull ffma2(ull a, ull b, ull c) {
    ull d; asm("fma.rn.f32x2 %0, %1, %2, %3;" : "=l"(d) : "l"(a), "l"(b), "l"(c)); return d;
}
__device__ __forceinline__ ull fmul2(ull a, ull b) {
    ull d; asm("mul.rn.f32x2 %0, %1, %2;" : "=l"(d) : "l"(a), "l"(b)); return d;
}
__device__ __forceinline__ ull fadd2(ull a, ull b) {
    ull d; asm("add.rn.f32x2 %0, %1, %2;" : "=l"(d) : "l"(a), "l"(b)); return d;
}
__device__ __forceinline__ ull pack2(float lo, float hi) {
    ull d; asm("mov.b64 %0, {%1, %2};" : "=l"(d) : "f"(lo), "f"(hi)); return d;
}
__device__ __forceinline__ void unpack2(ull a, float& lo, float& hi) {
    asm("mov.b64 {%0, %1}, %2;" : "=f"(lo), "=f"(hi) : "l"(a));
}

// ---- scratch (device globals; no allocation allowed) ----
__device__ float g_Qc[BH*T*S];     // compacted, scaled Q  [b][h][rank][s]
__device__ float g_Kc[BH*T*S];     // compacted, scaled K
__device__ float g_Vc[BH*T*S];     // compacted V
__device__ float g_AttnO[B*T*E];   // attention output (pre-projection)
__device__ float g_WuT[E*E];       // Wu transposed
__device__ int   g_idx[B*T];       // compacted j -> original t
__device__ int   g_rank[B*T];      // original t -> compacted j (or -1)
__device__ int   g_cnt[B];         // unmasked count per batch
// split-K partials (fixed-base softmax: plain sums, no max bookkeeping)
__device__ float g_pL[KSPLIT*BH*T];
__device__ float g_pO[KSPLIT*BH*T*S];

// ------------------------------------------------------------------
// 1. Compaction (blocks 0..7) + Wu transpose (blocks 8..23), fused
// ------------------------------------------------------------------
__global__ void prep_kernel(const int* __restrict__ masks,
                            const float* __restrict__ Wu) {
    if (blockIdx.x >= B) {
        // Wu transpose: 16 blocks x 1024 threads = 16384 elements
        int i = (blockIdx.x - B) * 1024 + threadIdx.x;
        int r = i >> 7, c = i & 127;
        g_WuT[i] = Wu[c*E + r];
        return;
    }
    int b = blockIdx.x;
    int t = threadIdx.x;            // 1024 threads
    int v = (masks[b*T + t] != 0) ? 1 : 0;
    unsigned bal = __ballot_sync(0xffffffffu, v);
    int lane = t & 31, warp = t >> 5;
    int wprefix = __popc(bal & ((1u << lane) - 1u));
    __shared__ int wcnt[32];
    __shared__ int wbase[32];
    if (lane == 31) wcnt[warp] = wprefix + v;
    __syncthreads();
    if (t == 0) {
        int acc = 0;
        for (int w = 0; w < 32; w++) { wbase[w] = acc; acc += wcnt[w]; }
        g_cnt[b] = acc;
    }
    __syncthreads();
    int r = v ? (wbase[warp] + wprefix) : -1;
    g_rank[b*T + t] = r;
    if (v) g_idx[b*T + r] = t;
}

// ------------------------------------------------------------------
// 2. QKV projection per (b,t,h), compacted scatter; zero masked rows
// ------------------------------------------------------------------
__global__ __launch_bounds__(256) void qkv_kernel(
    const float* __restrict__ x, const int* __restrict__ masks,
    const float* __restrict__ Wq, const float* __restrict__ Wk,
    const float* __restrict__ Wv)
{
    __shared__ float sW[3][S*S];
    int tid = threadIdx.x;          // 256 = S*S
    sW[0][tid] = Wq[tid];
    sW[1][tid] = Wk[tid];
    sW[2][tid] = Wv[tid];
    __syncthreads();

    int gid = blockIdx.x * 256 + tid;   // (b*T + t)*H + h
    int h  = gid & 7;
    int bt = gid >> 3;
    int msk = masks[bt];
    if (!msk) {
        float4 z = make_float4(0.f, 0.f, 0.f, 0.f);
        float4* op = (float4*)(g_AttnO + bt*E + h*S);
        op[0] = z; op[1] = z; op[2] = z; op[3] = z;
        return;
    }
    float xr[S];
    const float4* xp = (const float4*)(x + bt*E + h*S);
#pragma unroll
    for (int i = 0; i < 4; i++) {
        float4 v = xp[i];
        xr[4*i] = v.x; xr[4*i+1] = v.y; xr[4*i+2] = v.z; xr[4*i+3] = v.w;
    }
    int r = g_rank[bt];
    int b = bt >> 10;
    int base = ((b*H + h)*T + r)*S;
    const float invs = 0.29730177875068026f;   // 128^-0.25

    float o[S];
    // Q
#pragma unroll
    for (int d = 0; d < S; d++) {
        float a = 0.f;
#pragma unroll
        for (int s2 = 0; s2 < S; s2++) a = fmaf(sW[0][d*S + s2], xr[s2], a);
        o[d] = a * invs;
    }
    {
        float4* qp = (float4*)(g_Qc + base);
#pragma unroll
        for (int i = 0; i < 4; i++) qp[i] = make_float4(o[4*i], o[4*i+1], o[4*i+2], o[4*i+3]);
    }
    // K
#pragma unroll
    for (int d = 0; d < S; d++) {
        float a = 0.f;
#pragma unroll
        for (int s2 = 0; s2 < S; s2++) a = fmaf(sW[1][d*S + s2], xr[s2], a);
        o[d] = a * invs;
    }
    {
        float4* kp = (float4*)(g_Kc + base);
#pragma unroll
        for (int i = 0; i < 4; i++) kp[i] = make_float4(o[4*i], o[4*i+1], o[4*i+2], o[4*i+3]);
    }
    // V
#pragma unroll
    for (int d = 0; d < S; d++) {
        float a = 0.f;
#pragma unroll
        for (int s2 = 0; s2 < S; s2++) a = fmaf(sW[2][d*S + s2], xr[s2], a);
        o[d] = a;
    }
    {
        float4* vp = (float4*)(g_Vc + base);
#pragma unroll
        for (int i = 0; i < 4; i++) vp[i] = make_float4(o[4*i], o[4*i+1], o[4*i+2], o[4*i+3]);
    }
}

// ------------------------------------------------------------------
// 3. Attention, fixed-base softmax, split-K, FFMA2 inner loop
//    __launch_bounds__(64, 8): cap regs at 128 -> 16 warps/SM
// ------------------------------------------------------------------
#define ATH   64              // threads per block
#define QPT   2               // queries per thread
#define QBLK  (ATH*QPT)       // 128 queries per block
#define KTILE 128

__global__ __launch_bounds__(ATH, 8) void attn_split_kernel() {
    __shared__ float4 sK[KTILE][5];   // [5] pad
    __shared__ float4 sV[KTILE][5];

    int bh = blockIdx.y;
    int ks = blockIdx.z;
    int b  = bh >> 3;
    int cnt = g_cnt[b];
    if ((int)(blockIdx.x * QBLK) >= cnt) return;
    int k0 = (ks * cnt) / KSPLIT;
    int k1 = ((ks + 1) * cnt) / KSPLIT;
    int tid = threadIdx.x;

    const float* Qb = g_Qc + bh*T*S;
    const float* Kb = g_Kc + bh*T*S;
    const float* Vb = g_Vc + bh*T*S;

    int jj[QPT];
    ull qq[QPT][8], oo[QPT][8];
    float l[QPT];
#pragma unroll
    for (int p = 0; p < QPT; p++) {
        jj[p] = blockIdx.x*QBLK + tid + p*ATH;
        const ull* qp = (const ull*)(Qb + jj[p]*S);   // jj[p] < T always
#pragma unroll
        for (int i = 0; i < 8; i++) { qq[p][i] = qp[i]; oo[p][i] = 0ULL; }
        l[p] = 0.f;
    }
    bool active = jj[0] < cnt;   // warp-uniform granularity for tail blocks

    for (int kt = k0; kt < k1; kt += KTILE) {
        int nk = min(KTILE, k1 - kt);
        __syncthreads();
        for (int rr = tid; rr < nk; rr += ATH) {
            const float4* kp = (const float4*)(Kb + (kt+rr)*S);
            const float4* vp = (const float4*)(Vb + (kt+rr)*S);
#pragma unroll
            for (int c = 0; c < 4; c++) { sK[rr][c] = kp[c]; sV[rr][c] = vp[c]; }
        }
        __syncthreads();
        if (active) {
            for (int kk = 0; kk < nk; kk++) {
                const ull* kr = (const ull*)(&sK[kk][0]);
                const ull* vr = (const ull*)(&sV[kk][0]);
                ull kv0 = kr[0], kv1 = kr[1], kv2 = kr[2], kv3 = kr[3];
                ull kv4 = kr[4], kv5 = kr[5], kv6 = kr[6], kv7 = kr[7];
                ull vv0 = vr[0], vv1 = vr[1], vv2 = vr[2], vv3 = vr[3];
                ull vv4 = vr[4], vv5 = vr[5], vv6 = vr[6], vv7 = vr[7];
#pragma unroll
                for (int p = 0; p < QPT; p++) {
                    ull a0 = fmul2(qq[p][0], kv0);
                    ull a1 = fmul2(qq[p][1], kv1);
                    a0 = ffma2(qq[p][2], kv2, a0);
                    a1 = ffma2(qq[p][3], kv3, a1);
                    a0 = ffma2(qq[p][4], kv4, a0);
                    a1 = ffma2(qq[p][5], kv5, a1);
                    a0 = ffma2(qq[p][6], kv6, a0);
                    a1 = ffma2(qq[p][7], kv7, a1);
                    a0 = fadd2(a0, a1);
                    float lo, hi; unpack2(a0, lo, hi);
                    float w = __expf(lo + hi);
                    l[p] += w;
                    ull wp = pack2(w, w);
                    oo[p][0] = ffma2(wp, vv0, oo[p][0]);
                    oo[p][1] = ffma2(wp, vv1, oo[p][1]);
                    oo[p][2] = ffma2(wp, vv2, oo[p][2]);
                    oo[p][3] = ffma2(wp, vv3, oo[p][3]);
                    oo[p][4] = ffma2(wp, vv4, oo[p][4]);
                    oo[p][5] = ffma2(wp, vv5, oo[p][5]);
                    oo[p][6] = ffma2(wp, vv6, oo[p][6]);
                    oo[p][7] = ffma2(wp, vv7, oo[p][7]);
                }
            }
        }
    }

    // store unnormalized partial sums
#pragma unroll
    for (int p = 0; p < QPT; p++) {
        if (jj[p] < cnt) {
            int base = (ks*BH + bh)*T + jj[p];
            g_pL[base] = l[p];
            ull* op = (ull*)(g_pO + base*S);
#pragma unroll
            for (int i = 0; i < 8; i++) op[i] = oo[p][i];
        }
    }
}

// ------------------------------------------------------------------
// 3b. Combine split-K partials -> g_AttnO (plain sums + normalize)
// ------------------------------------------------------------------
__global__ __launch_bounds__(256) void attn_combine_kernel() {
    int g = blockIdx.x * 256 + threadIdx.x;   // bh*T + j
    int j  = g & (T-1);
    int bh = g >> 10;
    int b  = bh >> 3;
    if (j >= g_cnt[b]) return;

    float L = 0.f;
    ull acc[8];
#pragma unroll
    for (int i = 0; i < 8; i++) acc[i] = 0ULL;
#pragma unroll
    for (int ks = 0; ks < KSPLIT; ks++) {
        int base = (ks*BH + bh)*T + j;
        L += g_pL[base];
        const ull* op = (const ull*)(g_pO + base*S);
#pragma unroll
        for (int i = 0; i < 8; i++) acc[i] = fadd2(acc[i], op[i]);
    }
    float invL = (L > 0.f) ? (1.0f / L) : 0.f;
    ull il2 = pack2(invL, invL);
    int t = g_idx[b*T + j];
    ull* outp = (ull*)(g_AttnO + (b*T + t)*E + (bh & 7)*S);
#pragma unroll
    for (int i = 0; i < 8; i++) outp[i] = fmul2(acc[i], il2);
}

// ------------------------------------------------------------------
// 4. Output projection: out = AttnO @ Wu^T + bu  (WuT from global, L1-cached)
// ------------------------------------------------------------------
#define PR 16
__global__ __launch_bounds__(512) void proj_kernel(const float* __restrict__ bu,
                                                   float* __restrict__ out) {
    __shared__ float xs[PR][E];
    int tid = threadIdx.x;        // 512
    int rowbase = blockIdx.x * PR;
    const float* src = g_AttnO + rowbase*E;
    for (int i = tid; i < PR*E; i += 512) xs[i >> 7][i & 127] = src[i];
    __syncthreads();

    int row = tid >> 5;           // 0..15 (warp-uniform -> smem broadcast)
    int cg  = (tid & 31) * 4;     // column group
    float ax = 0.f, ay = 0.f, az = 0.f, aw = 0.f;
#pragma unroll 8
    for (int i = 0; i < E; i++) {
        float xv = xs[row][i];
        float4 w = *(const float4*)(g_WuT + i*E + cg);
        ax = fmaf(xv, w.x, ax); ay = fmaf(xv, w.y, ay);
        az = fmaf(xv, w.z, az); aw = fmaf(xv, w.w, aw);
    }
    float4 bb = *(const float4*)(bu + cg);
    *(float4*)(out + (rowbase + row)*E + cg) =
        make_float4(ax + bb.x, ay + bb.y, az + bb.z, aw + bb.w);
}

// ------------------------------------------------------------------
extern "C" void kernel_launch(void* const* d_in, const int* in_sizes, int n_in,
                              void* d_out, int out_size) {
    const float* x     = (const float*)d_in[0];
    const int*   masks = (const int*)  d_in[1];
    const float* Wq    = (const float*)d_in[2];
    const float* Wk    = (const float*)d_in[3];
    const float* Wv    = (const float*)d_in[4];
    const float* Wu    = (const float*)d_in[5];
    const float* bu    = (const float*)d_in[6];
    float* out = (float*)d_out;

    prep_kernel<<<B + 16, 1024>>>(masks, Wu);
    qkv_kernel<<<(B*T*H)/256, 256>>>(x, masks, Wq, Wk, Wv);
    attn_split_kernel<<<dim3(T/QBLK, BH, KSPLIT), ATH>>>();
    attn_combine_kernel<<<(BH*T)/256, 256>>>();
    proj_kernel<<<(B*T)/PR, 512>>>(bu, out);
}

// round 9
// speedup vs baseline: 2.3030x; 1.0703x over previous
#include <cuda_runtime.h>

#define B 8
#define T 1024
#define E 128
#define H 8
#define S 16
#define BH (B*H)
#define KSPLIT 8

// ---- packed f32x2 helpers (sm_103a FFMA2 path, PTX-only) ----
typedef unsigned long long ull;
__device__ __forceinline__ ull ffma2(ull a, ull b, ull c) {
    ull d; asm("fma.rn.f32x2 %0, %1, %2, %3;" : "=l"(d) : "l"(a), "l"(b), "l"(c)); return d;
}
__device__ __forceinline__ ull fmul2(ull a, ull b) {
    ull d; asm("mul.rn.f32x2 %0, %1, %2;" : "=l"(d) : "l"(a), "l"(b)); return d;
}
__device__ __forceinline__ ull fadd2(ull a, ull b) {
    ull d; asm("add.rn.f32x2 %0, %1, %2;" : "=l"(d) : "l"(a), "l"(b)); return d;
}
__device__ __forceinline__ ull pack2(float lo, float hi) {
    ull d; asm("mov.b64 %0, {%1, %2};" : "=l"(d) : "f"(lo), "f"(hi)); return d;
}
__device__ __forceinline__ void unpack2(ull a, float& lo, float& hi) {
    asm("mov.b64 {%0, %1}, %2;" : "=f"(lo), "=f"(hi) : "l"(a));
}
// 128-bit shared load -> two 64-bit pair registers (one LDS.128)
__device__ __forceinline__ void lds2(ull& a, ull& b, unsigned addr) {
    asm("ld.shared.v2.b64 {%0, %1}, [%2];" : "=l"(a), "=l"(b) : "r"(addr));
}

// ---- scratch (device globals; no allocation allowed) ----
__device__ float g_Qc[BH*T*S];     // compacted, scaled Q  [b][h][rank][s]
__device__ float g_Kc[BH*T*S];     // compacted, scaled K
__device__ float g_Vc[BH*T*S];     // compacted V
__device__ float g_WuT[E*E];       // Wu transposed
__device__ int   g_idx[B*T];       // compacted j -> original t
__device__ int   g_rank[B*T];      // original t -> compacted j (or -1)
__device__ int   g_cnt[B];         // unmasked count per batch
// split-K partials (fixed-base softmax: plain sums)
__device__ float g_pL[KSPLIT*BH*T];
__device__ float g_pO[KSPLIT*BH*T*S];

// ------------------------------------------------------------------
// 1. Compaction (blocks 0..7) + Wu transpose (blocks 8..23), fused
// ------------------------------------------------------------------
__global__ void prep_kernel(const int* __restrict__ masks,
                            const float* __restrict__ Wu) {
    if (blockIdx.x >= B) {
        int i = (blockIdx.x - B) * 1024 + threadIdx.x;
        int r = i >> 7, c = i & 127;
        g_WuT[i] = Wu[c*E + r];
        return;
    }
    int b = blockIdx.x;
    int t = threadIdx.x;            // 1024 threads
    int v = (masks[b*T + t] != 0) ? 1 : 0;
    unsigned bal = __ballot_sync(0xffffffffu, v);
    int lane = t & 31, warp = t >> 5;
    int wprefix = __popc(bal & ((1u << lane) - 1u));
    __shared__ int wcnt[32];
    __shared__ int wbase[32];
    if (lane == 31) wcnt[warp] = wprefix + v;
    __syncthreads();
    if (t == 0) {
        int acc = 0;
        for (int w = 0; w < 32; w++) { wbase[w] = acc; acc += wcnt[w]; }
        g_cnt[b] = acc;
    }
    __syncthreads();
    int r = v ? (wbase[warp] + wprefix) : -1;
    g_rank[b*T + t] = r;
    if (v) g_idx[b*T + r] = t;
}

// ------------------------------------------------------------------
// 2. QKV projection per (b,t,h), compacted scatter
// ------------------------------------------------------------------
__global__ __launch_bounds__(256) void qkv_kernel(
    const float* __restrict__ x, const int* __restrict__ masks,
    const float* __restrict__ Wq, const float* __restrict__ Wk,
    const float* __restrict__ Wv)
{
    __shared__ float sW[3][S*S];
    int tid = threadIdx.x;          // 256 = S*S
    sW[0][tid] = Wq[tid];
    sW[1][tid] = Wk[tid];
    sW[2][tid] = Wv[tid];
    __syncthreads();

    int gid = blockIdx.x * 256 + tid;   // (b*T + t)*H + h
    int h  = gid & 7;
    int bt = gid >> 3;
    if (!masks[bt]) return;             // proj zeroes masked rows via g_rank
    float xr[S];
    const float4* xp = (const float4*)(x + bt*E + h*S);
#pragma unroll
    for (int i = 0; i < 4; i++) {
        float4 v = xp[i];
        xr[4*i] = v.x; xr[4*i+1] = v.y; xr[4*i+2] = v.z; xr[4*i+3] = v.w;
    }
    int r = g_rank[bt];
    int b = bt >> 10;
    int base = ((b*H + h)*T + r)*S;
    const float invs = 0.29730177875068026f;   // 128^-0.25

    float o[S];
#pragma unroll
    for (int d = 0; d < S; d++) {
        float a = 0.f;
#pragma unroll
        for (int s2 = 0; s2 < S; s2++) a = fmaf(sW[0][d*S + s2], xr[s2], a);
        o[d] = a * invs;
    }
    {
        float4* qp = (float4*)(g_Qc + base);
#pragma unroll
        for (int i = 0; i < 4; i++) qp[i] = make_float4(o[4*i], o[4*i+1], o[4*i+2], o[4*i+3]);
    }
#pragma unroll
    for (int d = 0; d < S; d++) {
        float a = 0.f;
#pragma unroll
        for (int s2 = 0; s2 < S; s2++) a = fmaf(sW[1][d*S + s2], xr[s2], a);
        o[d] = a * invs;
    }
    {
        float4* kp = (float4*)(g_Kc + base);
#pragma unroll
        for (int i = 0; i < 4; i++) kp[i] = make_float4(o[4*i], o[4*i+1], o[4*i+2], o[4*i+3]);
    }
#pragma unroll
    for (int d = 0; d < S; d++) {
        float a = 0.f;
#pragma unroll
        for (int s2 = 0; s2 < S; s2++) a = fmaf(sW[2][d*S + s2], xr[s2], a);
        o[d] = a;
    }
    {
        float4* vp = (float4*)(g_Vc + base);
#pragma unroll
        for (int i = 0; i < 4; i++) vp[i] = make_float4(o[4*i], o[4*i+1], o[4*i+2], o[4*i+3]);
    }
}

// ------------------------------------------------------------------
// 3. Attention, fixed-base softmax, split-K, FFMA2 + LDS.128 inner loop
// ------------------------------------------------------------------
#define ATH   64              // threads per block
#define QPT   2               // queries per thread
#define QBLK  (ATH*QPT)       // 128 queries per block
#define KTILE 128

__global__ __launch_bounds__(ATH, 8) void attn_split_kernel() {
    __shared__ float4 sK[KTILE][5];   // 80B row stride
    __shared__ float4 sV[KTILE][5];

    int bh = blockIdx.y;
    int ks = blockIdx.z;
    int b  = bh >> 3;
    int cnt = g_cnt[b];
    if ((int)(blockIdx.x * QBLK) >= cnt) return;
    int k0 = (ks * cnt) / KSPLIT;
    int k1 = ((ks + 1) * cnt) / KSPLIT;
    int tid = threadIdx.x;

    const float* Qb = g_Qc + bh*T*S;
    const float* Kb = g_Kc + bh*T*S;
    const float* Vb = g_Vc + bh*T*S;

    unsigned skb = (unsigned)__cvta_generic_to_shared(&sK[0][0]);
    unsigned svb = (unsigned)__cvta_generic_to_shared(&sV[0][0]);

    int jj[QPT];
    ull qq[QPT][8], oo[QPT][8];
    float l[QPT];
#pragma unroll
    for (int p = 0; p < QPT; p++) {
        jj[p] = blockIdx.x*QBLK + tid + p*ATH;
        const ull* qp = (const ull*)(Qb + jj[p]*S);   // jj[p] < T always
#pragma unroll
        for (int i = 0; i < 8; i++) { qq[p][i] = qp[i]; oo[p][i] = 0ULL; }
        l[p] = 0.f;
    }
    bool active = jj[0] < cnt;

    for (int kt = k0; kt < k1; kt += KTILE) {
        int nk = min(KTILE, k1 - kt);
        __syncthreads();
        for (int rr = tid; rr < nk; rr += ATH) {
            const float4* kp = (const float4*)(Kb + (kt+rr)*S);
            const float4* vp = (const float4*)(Vb + (kt+rr)*S);
#pragma unroll
            for (int c = 0; c < 4; c++) { sK[rr][c] = kp[c]; sV[rr][c] = vp[c]; }
        }
        __syncthreads();
        if (active) {
            for (int kk = 0; kk < nk; kk++) {
                unsigned ka = skb + kk*80u;
                unsigned va = svb + kk*80u;
                ull kv0, kv1, kv2, kv3, kv4, kv5, kv6, kv7;
                ull vv0, vv1, vv2, vv3, vv4, vv5, vv6, vv7;
                lds2(kv0, kv1, ka);      lds2(kv2, kv3, ka + 16u);
                lds2(kv4, kv5, ka + 32u); lds2(kv6, kv7, ka + 48u);
                lds2(vv0, vv1, va);      lds2(vv2, vv3, va + 16u);
                lds2(vv4, vv5, va + 32u); lds2(vv6, vv7, va + 48u);
#pragma unroll
                for (int p = 0; p < QPT; p++) {
                    ull a0 = fmul2(qq[p][0], kv0);
                    ull a1 = fmul2(qq[p][1], kv1);
                    a0 = ffma2(qq[p][2], kv2, a0);
                    a1 = ffma2(qq[p][3], kv3, a1);
                    a0 = ffma2(qq[p][4], kv4, a0);
                    a1 = ffma2(qq[p][5], kv5, a1);
                    a0 = ffma2(qq[p][6], kv6, a0);
                    a1 = ffma2(qq[p][7], kv7, a1);
                    a0 = fadd2(a0, a1);
                    float lo, hi; unpack2(a0, lo, hi);
                    float w = __expf(lo + hi);
                    l[p] += w;
                    ull wp = pack2(w, w);
                    oo[p][0] = ffma2(wp, vv0, oo[p][0]);
                    oo[p][1] = ffma2(wp, vv1, oo[p][1]);
                    oo[p][2] = ffma2(wp, vv2, oo[p][2]);
                    oo[p][3] = ffma2(wp, vv3, oo[p][3]);
                    oo[p][4] = ffma2(wp, vv4, oo[p][4]);
                    oo[p][5] = ffma2(wp, vv5, oo[p][5]);
                    oo[p][6] = ffma2(wp, vv6, oo[p][6]);
                    oo[p][7] = ffma2(wp, vv7, oo[p][7]);
                }
            }
        }
    }

#pragma unroll
    for (int p = 0; p < QPT; p++) {
        if (jj[p] < cnt) {
            int base = (ks*BH + bh)*T + jj[p];
            g_pL[base] = l[p];
            ull* op = (ull*)(g_pO + base*S);
#pragma unroll
            for (int i = 0; i < 8; i++) op[i] = oo[p][i];
        }
    }
}

// ------------------------------------------------------------------
// 4. Fused combine + projection: gather split partials, normalize,
//    then out = AttnO @ Wu^T + bu   (AttnO never materialized)
// ------------------------------------------------------------------
#define PR 16
__global__ __launch_bounds__(512) void proj_kernel(const float* __restrict__ bu,
                                                   float* __restrict__ out) {
    __shared__ float xs[PR][E];
    int tid = threadIdx.x;        // 512
    int rowbase = blockIdx.x * PR;
    int row  = tid >> 5;          // 0..15 (== warp id)
    int lane = tid & 31;
    int bt = rowbase + row;
    int b  = bt >> 10;
    int j  = g_rank[bt];          // broadcast within warp

    // gather phase: each thread produces 2 ull (4 floats) of this row
    int u  = lane * 2;            // ull index 0..62
    int h  = u >> 3;              // same h for both ull of this thread
    int d4 = u & 7;               // even
    ull* xrow = (ull*)&xs[row][0];
    if (j < 0) {
        xrow[u]   = 0ULL;
        xrow[u+1] = 0ULL;
    } else {
        int bh = b*H + h;
        float L = 0.f;
        ull acc0 = 0ULL, acc1 = 0ULL;
#pragma unroll
        for (int ks = 0; ks < KSPLIT; ks++) {
            int base = (ks*BH + bh)*T + j;
            L += g_pL[base];
            float4 v = *(const float4*)(g_pO + base*S + d4*2);
            acc0 = fadd2(acc0, pack2(v.x, v.y));
            acc1 = fadd2(acc1, pack2(v.z, v.w));
        }
        float invL = (L > 0.f) ? (1.0f / L) : 0.f;
        ull il2 = pack2(invL, invL);
        xrow[u]   = fmul2(acc0, il2);
        xrow[u+1] = fmul2(acc1, il2);
    }
    __syncthreads();

    // GEMM phase: row uniform per warp -> smem broadcast reads
    int cg = lane * 4;
    float ax = 0.f, ay = 0.f, az = 0.f, aw = 0.f;
#pragma unroll 8
    for (int i = 0; i < E; i++) {
        float xv = xs[row][i];
        float4 w = *(const float4*)(g_WuT + i*E + cg);
        ax = fmaf(xv, w.x, ax); ay = fmaf(xv, w.y, ay);
        az = fmaf(xv, w.z, az); aw = fmaf(xv, w.w, aw);
    }
    float4 bb = *(const float4*)(bu + cg);
    *(float4*)(out + bt*E + cg) =
        make_float4(ax + bb.x, ay + bb.y, az + bb.z, aw + bb.w);
}

// ------------------------------------------------------------------
extern "C" void kernel_launch(void* const* d_in, const int* in_sizes, int n_in,
                              void* d_out, int out_size) {
    const float* x     = (const float*)d_in[0];
    const int*   masks = (const int*)  d_in[1];
    const float* Wq    = (const float*)d_in[2];
    const float* Wk    = (const float*)d_in[3];
    const float* Wv    = (const float*)d_in[4];
    const float* Wu    = (const float*)d_in[5];
    const float* bu    = (const float*)d_in[6];
    float* out = (float*)d_out;

    prep_kernel<<<B + 16, 1024>>>(masks, Wu);
    qkv_kernel<<<(B*T*H)/256, 256>>>(x, masks, Wq, Wk, Wv);
    attn_split_kernel<<<dim3(T/QBLK, BH, KSPLIT), ATH>>>();
    proj_kernel<<<(B*T)/PR, 512>>>(bu, out);
}

// round 10
// speedup vs baseline: 2.6046x; 1.1310x over previous
#include <cuda_runtime.h>

#define B 8
#define T 1024
#define E 128
#define H 8
#define S 16
#define BH (B*H)
#define KSPLIT 8

// ---- packed f32x2 helpers (sm_103a FFMA2 path, PTX-only) ----
typedef unsigned long long ull;
__device__ __forceinline__ ull ffma2(ull a, ull b, ull c) {
    ull d; asm("fma.rn.f32x2 %0, %1, %2, %3;" : "=l"(d) : "l"(a), "l"(b), "l"(c)); return d;
}
__device__ __forceinline__ ull fmul2(ull a, ull b) {
    ull d; asm("mul.rn.f32x2 %0, %1, %2;" : "=l"(d) : "l"(a), "l"(b)); return d;
}
__device__ __forceinline__ ull fadd2(ull a, ull b) {
    ull d; asm("add.rn.f32x2 %0, %1, %2;" : "=l"(d) : "l"(a), "l"(b)); return d;
}
__device__ __forceinline__ ull pack2(float lo, float hi) {
    ull d; asm("mov.b64 %0, {%1, %2};" : "=l"(d) : "f"(lo), "f"(hi)); return d;
}
__device__ __forceinline__ void unpack2(ull a, float& lo, float& hi) {
    asm("mov.b64 {%0, %1}, %2;" : "=f"(lo), "=f"(hi) : "l"(a));
}
__device__ __forceinline__ void lds2(ull& a, ull& b, unsigned addr) {
    asm("ld.shared.v2.b64 {%0, %1}, [%2];" : "=l"(a), "=l"(b) : "r"(addr));
}
__device__ __forceinline__ float ex2(float x) {
    float y; asm("ex2.approx.f32 %0, %1;" : "=f"(y) : "f"(x)); return y;
}

// ---- scratch (device globals; no allocation allowed) ----
__device__ float g_Qc[BH*T*S];     // compacted Q, scaled by 128^-0.25 * log2(e)
__device__ float g_Kc[BH*T*S];     // compacted K, scaled by 128^-0.25
__device__ float g_Vc[BH*T*S];     // compacted V
__device__ float g_WuT[E*E];       // Wu transposed
__device__ int   g_idx[B*T];       // compacted j -> original t
__device__ int   g_rank[B*T];      // original t -> compacted j (or -1)
__device__ int   g_cnt[B];         // unmasked count per batch
// split-K partials (fixed-base softmax: plain sums)
__device__ float g_pL[KSPLIT*BH*T];
__device__ float g_pO[KSPLIT*BH*T*S];

// ------------------------------------------------------------------
// 1. Compaction (blocks 0..7) + Wu transpose (blocks 8..23), fused
// ------------------------------------------------------------------
__global__ void prep_kernel(const int* __restrict__ masks,
                            const float* __restrict__ Wu) {
    if (blockIdx.x >= B) {
        int i = (blockIdx.x - B) * 1024 + threadIdx.x;
        int r = i >> 7, c = i & 127;
        g_WuT[i] = Wu[c*E + r];
        return;
    }
    int b = blockIdx.x;
    int t = threadIdx.x;            // 1024 threads
    int v = (masks[b*T + t] != 0) ? 1 : 0;
    unsigned bal = __ballot_sync(0xffffffffu, v);
    int lane = t & 31, warp = t >> 5;
    int wprefix = __popc(bal & ((1u << lane) - 1u));
    __shared__ int wcnt[32];
    __shared__ int wbase[32];
    if (lane == 31) wcnt[warp] = wprefix + v;
    __syncthreads();
    if (t == 0) {
        int acc = 0;
        for (int w = 0; w < 32; w++) { wbase[w] = acc; acc += wcnt[w]; }
        g_cnt[b] = acc;
    }
    __syncthreads();
    int r = v ? (wbase[warp] + wprefix) : -1;
    g_rank[b*T + t] = r;
    if (v) g_idx[b*T + r] = t;
}

// ------------------------------------------------------------------
// 2. QKV projection; masked rows write out = bu directly
// ------------------------------------------------------------------
__global__ __launch_bounds__(256) void qkv_kernel(
    const float* __restrict__ x, const int* __restrict__ masks,
    const float* __restrict__ Wq, const float* __restrict__ Wk,
    const float* __restrict__ Wv, const float* __restrict__ bu,
    float* __restrict__ out)
{
    __shared__ float sW[3][S*S];
    int tid = threadIdx.x;          // 256 = S*S
    sW[0][tid] = Wq[tid];
    sW[1][tid] = Wk[tid];
    sW[2][tid] = Wv[tid];
    __syncthreads();

    int gid = blockIdx.x * 256 + tid;   // (b*T + t)*H + h
    int h  = gid & 7;
    int bt = gid >> 3;
    if (!masks[bt]) {
        const float4* bb = (const float4*)(bu + h*S);
        float4* op = (float4*)(out + bt*E + h*S);
#pragma unroll
        for (int i = 0; i < 4; i++) op[i] = bb[i];
        return;
    }
    float xr[S];
    const float4* xp = (const float4*)(x + bt*E + h*S);
#pragma unroll
    for (int i = 0; i < 4; i++) {
        float4 v = xp[i];
        xr[4*i] = v.x; xr[4*i+1] = v.y; xr[4*i+2] = v.z; xr[4*i+3] = v.w;
    }
    int r = g_rank[bt];
    int b = bt >> 10;
    int base = ((b*H + h)*T + r)*S;
    const float invs   = 0.29730177875068026f;                       // 128^-0.25
    const float invs_q = 0.29730177875068026f * 1.4426950408889634f; // * log2(e)

    float o[S];
#pragma unroll
    for (int d = 0; d < S; d++) {
        float a = 0.f;
#pragma unroll
        for (int s2 = 0; s2 < S; s2++) a = fmaf(sW[0][d*S + s2], xr[s2], a);
        o[d] = a * invs_q;
    }
    {
        float4* qp = (float4*)(g_Qc + base);
#pragma unroll
        for (int i = 0; i < 4; i++) qp[i] = make_float4(o[4*i], o[4*i+1], o[4*i+2], o[4*i+3]);
    }
#pragma unroll
    for (int d = 0; d < S; d++) {
        float a = 0.f;
#pragma unroll
        for (int s2 = 0; s2 < S; s2++) a = fmaf(sW[1][d*S + s2], xr[s2], a);
        o[d] = a * invs;
    }
    {
        float4* kp = (float4*)(g_Kc + base);
#pragma unroll
        for (int i = 0; i < 4; i++) kp[i] = make_float4(o[4*i], o[4*i+1], o[4*i+2], o[4*i+3]);
    }
#pragma unroll
    for (int d = 0; d < S; d++) {
        float a = 0.f;
#pragma unroll
        for (int s2 = 0; s2 < S; s2++) a = fmaf(sW[2][d*S + s2], xr[s2], a);
        o[d] = a;
    }
    {
        float4* vp = (float4*)(g_Vc + base);
#pragma unroll
        for (int i = 0; i < 4; i++) vp[i] = make_float4(o[4*i], o[4*i+1], o[4*i+2], o[4*i+3]);
    }
}

// ------------------------------------------------------------------
// 3. Attention, fixed-base softmax (exp2), split-K, FFMA2 + LDS.128
// ------------------------------------------------------------------
#define ATH   64
#define QPT   2
#define QBLK  (ATH*QPT)
#define KTILE 128

__global__ __launch_bounds__(ATH, 8) void attn_split_kernel() {
    __shared__ float4 sK[KTILE][5];
    __shared__ float4 sV[KTILE][5];

    int bh = blockIdx.y;
    int ks = blockIdx.z;
    int b  = bh >> 3;
    int cnt = g_cnt[b];
    if ((int)(blockIdx.x * QBLK) >= cnt) return;
    int k0 = (ks * cnt) / KSPLIT;
    int k1 = ((ks + 1) * cnt) / KSPLIT;
    int tid = threadIdx.x;

    const float* Qb = g_Qc + bh*T*S;
    const float* Kb = g_Kc + bh*T*S;
    const float* Vb = g_Vc + bh*T*S;

    unsigned skb = (unsigned)__cvta_generic_to_shared(&sK[0][0]);
    unsigned svb = (unsigned)__cvta_generic_to_shared(&sV[0][0]);

    int jj[QPT];
    ull qq[QPT][8], oo[QPT][8];
    float l[QPT];
#pragma unroll
    for (int p = 0; p < QPT; p++) {
        jj[p] = blockIdx.x*QBLK + tid + p*ATH;
        const ull* qp = (const ull*)(Qb + jj[p]*S);
#pragma unroll
        for (int i = 0; i < 8; i++) { qq[p][i] = qp[i]; oo[p][i] = 0ULL; }
        l[p] = 0.f;
    }
    bool active = jj[0] < cnt;

    for (int kt = k0; kt < k1; kt += KTILE) {
        int nk = min(KTILE, k1 - kt);
        __syncthreads();
        for (int rr = tid; rr < nk; rr += ATH) {
            const float4* kp = (const float4*)(Kb + (kt+rr)*S);
            const float4* vp = (const float4*)(Vb + (kt+rr)*S);
#pragma unroll
            for (int c = 0; c < 4; c++) { sK[rr][c] = kp[c]; sV[rr][c] = vp[c]; }
        }
        __syncthreads();
        if (active) {
            for (int kk = 0; kk < nk; kk++) {
                unsigned ka = skb + kk*80u;
                unsigned va = svb + kk*80u;
                ull kv0, kv1, kv2, kv3, kv4, kv5, kv6, kv7;
                ull vv0, vv1, vv2, vv3, vv4, vv5, vv6, vv7;
                lds2(kv0, kv1, ka);       lds2(kv2, kv3, ka + 16u);
                lds2(kv4, kv5, ka + 32u); lds2(kv6, kv7, ka + 48u);
                lds2(vv0, vv1, va);       lds2(vv2, vv3, va + 16u);
                lds2(vv4, vv5, va + 32u); lds2(vv6, vv7, va + 48u);
#pragma unroll
                for (int p = 0; p < QPT; p++) {
                    ull a0 = fmul2(qq[p][0], kv0);
                    ull a1 = fmul2(qq[p][1], kv1);
                    a0 = ffma2(qq[p][2], kv2, a0);
                    a1 = ffma2(qq[p][3], kv3, a1);
                    a0 = ffma2(qq[p][4], kv4, a0);
                    a1 = ffma2(qq[p][5], kv5, a1);
                    a0 = ffma2(qq[p][6], kv6, a0);
                    a1 = ffma2(qq[p][7], kv7, a1);
                    a0 = fadd2(a0, a1);
                    float lo, hi; unpack2(a0, lo, hi);
                    float w = ex2(lo + hi);   // Q pre-scaled by log2(e)
                    l[p] += w;
                    ull wp = pack2(w, w);
                    oo[p][0] = ffma2(wp, vv0, oo[p][0]);
                    oo[p][1] = ffma2(wp, vv1, oo[p][1]);
                    oo[p][2] = ffma2(wp, vv2, oo[p][2]);
                    oo[p][3] = ffma2(wp, vv3, oo[p][3]);
                    oo[p][4] = ffma2(wp, vv4, oo[p][4]);
                    oo[p][5] = ffma2(wp, vv5, oo[p][5]);
                    oo[p][6] = ffma2(wp, vv6, oo[p][6]);
                    oo[p][7] = ffma2(wp, vv7, oo[p][7]);
                }
            }
        }
    }

#pragma unroll
    for (int p = 0; p < QPT; p++) {
        if (jj[p] < cnt) {
            int base = (ks*BH + bh)*T + jj[p];
            g_pL[base] = l[p];
            ull* op = (ull*)(g_pO + base*S);
#pragma unroll
            for (int i = 0; i < 8; i++) op[i] = oo[p][i];
        }
    }
}

// ------------------------------------------------------------------
// 4. Fused combine + projection over COMPACTED rows only.
// ------------------------------------------------------------------
#define PRJ 16
__global__ __launch_bounds__(256) void proj_kernel(const float* __restrict__ bu,
                                                   float* __restrict__ out) {
    __shared__ float xs[PRJ][E];
    __shared__ int   sidx[PRJ];
    int b = blockIdx.y;
    int cnt = g_cnt[b];
    int rowbase = blockIdx.x * PRJ;
    if (rowbase >= cnt) return;
    int tid = threadIdx.x;        // 256

    // ---- gather phase: thread -> (row, 8 floats of that row) ----
    {
        int row = tid >> 4;           // 0..15
        int j   = rowbase + row;
        int f0  = (tid & 15) * 8;     // 0,8,...,120
        int h   = f0 >> 4;
        if (j < cnt) {
            int bh = b*H + h;
            int off = f0 & 15;        // 0 or 8
            float L = 0.f;
            ull a0 = 0ULL, a1 = 0ULL, a2 = 0ULL, a3 = 0ULL;
#pragma unroll
            for (int ks = 0; ks < KSPLIT; ks++) {
                int base = (ks*BH + bh)*T + j;
                L += g_pL[base];
                const float4* p = (const float4*)(g_pO + base*S + off);
                float4 v0 = p[0], v1 = p[1];
                a0 = fadd2(a0, pack2(v0.x, v0.y));
                a1 = fadd2(a1, pack2(v0.z, v0.w));
                a2 = fadd2(a2, pack2(v1.x, v1.y));
                a3 = fadd2(a3, pack2(v1.z, v1.w));
            }
            float invL = (L > 0.f) ? (1.0f / L) : 0.f;
            ull il2 = pack2(invL, invL);
            ull* xr = (ull*)&xs[row][f0];
            xr[0] = fmul2(a0, il2); xr[1] = fmul2(a1, il2);
            xr[2] = fmul2(a2, il2); xr[3] = fmul2(a3, il2);
            if ((tid & 15) == 0) sidx[row] = g_idx[b*T + j];
        }
    }
    __syncthreads();

    // ---- GEMM phase: 128 threads, 4 rows x 4 cols per thread ----
    if (tid < 128) {
        int lane = tid & 31, rg = tid >> 5;   // rg warp-uniform
        int cg = lane * 4;
        ull acc[4][2];
#pragma unroll
        for (int r = 0; r < 4; r++) { acc[r][0] = 0ULL; acc[r][1] = 0ULL; }
#pragma unroll 4
        for (int i = 0; i < E; i++) {
            float4 w = *(const float4*)(g_WuT + i*E + cg);
            ull wp0 = pack2(w.x, w.y), wp1 = pack2(w.z, w.w);
#pragma unroll
            for (int r = 0; r < 4; r++) {
                float xv = xs[rg*4 + r][i];
                ull xp = pack2(xv, xv);
                acc[r][0] = ffma2(xp, wp0, acc[r][0]);
                acc[r][1] = ffma2(xp, wp1, acc[r][1]);
            }
        }
        float4 bb = *(const float4*)(bu + cg);
#pragma unroll
        for (int r = 0; r < 4; r++) {
            int j2 = rowbase + rg*4 + r;
            if (j2 < cnt) {
                int t = sidx[rg*4 + r];
                float o0, o1, o2, o3;
                unpack2(acc[r][0], o0, o1);
                unpack2(acc[r][1], o2, o3);
                *(float4*)(out + (b*T + t)*E + cg) =
                    make_float4(o0 + bb.x, o1 + bb.y, o2 + bb.z, o3 + bb.w);
            }
        }
    }
}

// ------------------------------------------------------------------
extern "C" void kernel_launch(void* const* d_in, const int* in_sizes, int n_in,
                              void* d_out, int out_size) {
    const float* x     = (const float*)d_in[0];
    const int*   masks = (const int*)  d_in[1];
    const float* Wq    = (const float*)d_in[2];
    const float* Wk    = (const float*)d_in[3];
    const float* Wv    = (const float*)d_in[4];
    const float* Wu    = (const float*)d_in[5];
    const float* bu    = (const float*)d_in[6];
    float* out = (float*)d_out;

    prep_kernel<<<B + 16, 1024>>>(masks, Wu);
    qkv_kernel<<<(B*T*H)/256, 256>>>(x, masks, Wq, Wk, Wv, bu, out);
    attn_split_kernel<<<dim3(T/QBLK, BH, KSPLIT), ATH>>>();
    proj_kernel<<<dim3(T/PRJ, B), 256>>>(bu, out);
}

// round 11
// speedup vs baseline: 2.6123x; 1.0029x over previous
#include <cuda_runtime.h>

#define B 8
#define T 1024
#define E 128
#define H 8
#define S 16
#define BH (B*H)
#define KSPLIT 8

// ---- packed f32x2 helpers (sm_103a FFMA2 path, PTX-only) ----
typedef unsigned long long ull;
__device__ __forceinline__ ull ffma2(ull a, ull b, ull c) {
    ull d; asm("fma.rn.f32x2 %0, %1, %2, %3;" : "=l"(d) : "l"(a), "l"(b), "l"(c)); return d;
}
__device__ __forceinline__ ull fmul2(ull a, ull b) {
    ull d; asm("mul.rn.f32x2 %0, %1, %2;" : "=l"(d) : "l"(a), "l"(b)); return d;
}
__device__ __forceinline__ ull fadd2(ull a, ull b) {
    ull d; asm("add.rn.f32x2 %0, %1, %2;" : "=l"(d) : "l"(a), "l"(b)); return d;
}
__device__ __forceinline__ ull pack2(float lo, float hi) {
    ull d; asm("mov.b64 %0, {%1, %2};" : "=l"(d) : "f"(lo), "f"(hi)); return d;
}
__device__ __forceinline__ void unpack2(ull a, float& lo, float& hi) {
    asm("mov.b64 {%0, %1}, %2;" : "=f"(lo), "=f"(hi) : "l"(a));
}
__device__ __forceinline__ void lds2(ull& a, ull& b, unsigned addr) {
    asm("ld.shared.v2.b64 {%0, %1}, [%2];" : "=l"(a), "=l"(b) : "r"(addr));
}
__device__ __forceinline__ float ex2(float x) {
    float y; asm("ex2.approx.f32 %0, %1;" : "=f"(y) : "f"(x)); return y;
}

// ---- scratch (device globals; no allocation allowed) ----
__device__ float g_Qc[BH*T*S];     // compacted Q, scaled by 128^-0.25 * log2(e)
__device__ float g_Kc[BH*T*S];     // compacted K, scaled by 128^-0.25
__device__ float g_Vc[BH*T*S];     // compacted V
__device__ float g_WuT[E*E];       // Wu transposed
__device__ int   g_idx[B*T];       // compacted j -> original t
__device__ int   g_rank[B*T];      // original t -> compacted j (or -1)
__device__ int   g_cnt[B];         // unmasked count per batch
// split-K partials (fixed-base softmax: plain sums)
__device__ float g_pL[KSPLIT*BH*T];
__device__ float g_pO[KSPLIT*BH*T*S];

// ------------------------------------------------------------------
// 1. Compaction (blocks 0..7) + Wu transpose (blocks 8..23), fused
// ------------------------------------------------------------------
__global__ void prep_kernel(const int* __restrict__ masks,
                            const float* __restrict__ Wu) {
    if (blockIdx.x >= B) {
        int i = (blockIdx.x - B) * 1024 + threadIdx.x;
        int r = i >> 7, c = i & 127;
        g_WuT[i] = Wu[c*E + r];
        return;
    }
    int b = blockIdx.x;
    int t = threadIdx.x;            // 1024 threads
    int v = (masks[b*T + t] != 0) ? 1 : 0;
    unsigned bal = __ballot_sync(0xffffffffu, v);
    int lane = t & 31, warp = t >> 5;
    int wprefix = __popc(bal & ((1u << lane) - 1u));
    __shared__ int wcnt[32];
    __shared__ int wbase[32];
    if (lane == 31) wcnt[warp] = wprefix + v;
    __syncthreads();
    if (t == 0) {
        int acc = 0;
        for (int w = 0; w < 32; w++) { wbase[w] = acc; acc += wcnt[w]; }
        g_cnt[b] = acc;
    }
    __syncthreads();
    int r = v ? (wbase[warp] + wprefix) : -1;
    g_rank[b*T + t] = r;
    if (v) g_idx[b*T + r] = t;
}

// ------------------------------------------------------------------
// 2. QKV projection; masked rows write out = bu directly
// ------------------------------------------------------------------
__global__ __launch_bounds__(256) void qkv_kernel(
    const float* __restrict__ x, const int* __restrict__ masks,
    const float* __restrict__ Wq, const float* __restrict__ Wk,
    const float* __restrict__ Wv, const float* __restrict__ bu,
    float* __restrict__ out)
{
    __shared__ float sW[3][S*S];
    int tid = threadIdx.x;          // 256 = S*S
    sW[0][tid] = Wq[tid];
    sW[1][tid] = Wk[tid];
    sW[2][tid] = Wv[tid];
    __syncthreads();

    int gid = blockIdx.x * 256 + tid;   // (b*T + t)*H + h
    int h  = gid & 7;
    int bt = gid >> 3;
    if (!masks[bt]) {
        const float4* bb = (const float4*)(bu + h*S);
        float4* op = (float4*)(out + bt*E + h*S);
#pragma unroll
        for (int i = 0; i < 4; i++) op[i] = bb[i];
        return;
    }
    float xr[S];
    const float4* xp = (const float4*)(x + bt*E + h*S);
#pragma unroll
    for (int i = 0; i < 4; i++) {
        float4 v = xp[i];
        xr[4*i] = v.x; xr[4*i+1] = v.y; xr[4*i+2] = v.z; xr[4*i+3] = v.w;
    }
    int r = g_rank[bt];
    int b = bt >> 10;
    int base = ((b*H + h)*T + r)*S;
    const float invs   = 0.29730177875068026f;                       // 128^-0.25
    const float invs_q = 0.29730177875068026f * 1.4426950408889634f; // * log2(e)

    float o[S];
#pragma unroll
    for (int d = 0; d < S; d++) {
        float a = 0.f;
#pragma unroll
        for (int s2 = 0; s2 < S; s2++) a = fmaf(sW[0][d*S + s2], xr[s2], a);
        o[d] = a * invs_q;
    }
    {
        float4* qp = (float4*)(g_Qc + base);
#pragma unroll
        for (int i = 0; i < 4; i++) qp[i] = make_float4(o[4*i], o[4*i+1], o[4*i+2], o[4*i+3]);
    }
#pragma unroll
    for (int d = 0; d < S; d++) {
        float a = 0.f;
#pragma unroll
        for (int s2 = 0; s2 < S; s2++) a = fmaf(sW[1][d*S + s2], xr[s2], a);
        o[d] = a * invs;
    }
    {
        float4* kp = (float4*)(g_Kc + base);
#pragma unroll
        for (int i = 0; i < 4; i++) kp[i] = make_float4(o[4*i], o[4*i+1], o[4*i+2], o[4*i+3]);
    }
#pragma unroll
    for (int d = 0; d < S; d++) {
        float a = 0.f;
#pragma unroll
        for (int s2 = 0; s2 < S; s2++) a = fmaf(sW[2][d*S + s2], xr[s2], a);
        o[d] = a;
    }
    {
        float4* vp = (float4*)(g_Vc + base);
#pragma unroll
        for (int i = 0; i < 4; i++) vp[i] = make_float4(o[4*i], o[4*i+1], o[4*i+2], o[4*i+3]);
    }
}

// ------------------------------------------------------------------
// 3. Attention, fixed-base softmax (exp2), split-K, FFMA2 + LDS.128
// ------------------------------------------------------------------
#define ATH   64
#define QPT   2
#define QBLK  (ATH*QPT)
#define KTILE 128

__global__ __launch_bounds__(ATH, 8) void attn_split_kernel() {
    __shared__ float4 sK[KTILE][5];
    __shared__ float4 sV[KTILE][5];

    int bh = blockIdx.y;
    int ks = blockIdx.z;
    int b  = bh >> 3;
    int cnt = g_cnt[b];
    if ((int)(blockIdx.x * QBLK) >= cnt) return;
    int k0 = (ks * cnt) / KSPLIT;
    int k1 = ((ks + 1) * cnt) / KSPLIT;
    int tid = threadIdx.x;

    const float* Qb = g_Qc + bh*T*S;
    const float* Kb = g_Kc + bh*T*S;
    const float* Vb = g_Vc + bh*T*S;

    unsigned skb = (unsigned)__cvta_generic_to_shared(&sK[0][0]);
    unsigned svb = (unsigned)__cvta_generic_to_shared(&sV[0][0]);

    int jj[QPT];
    ull qq[QPT][8], oo[QPT][8];
    float l[QPT];
#pragma unroll
    for (int p = 0; p < QPT; p++) {
        jj[p] = blockIdx.x*QBLK + tid + p*ATH;
        const ull* qp = (const ull*)(Qb + jj[p]*S);
#pragma unroll
        for (int i = 0; i < 8; i++) { qq[p][i] = qp[i]; oo[p][i] = 0ULL; }
        l[p] = 0.f;
    }
    bool active = jj[0] < cnt;

    for (int kt = k0; kt < k1; kt += KTILE) {
        int nk = min(KTILE, k1 - kt);
        __syncthreads();
        for (int rr = tid; rr < nk; rr += ATH) {
            const float4* kp = (const float4*)(Kb + (kt+rr)*S);
            const float4* vp = (const float4*)(Vb + (kt+rr)*S);
#pragma unroll
            for (int c = 0; c < 4; c++) { sK[rr][c] = kp[c]; sV[rr][c] = vp[c]; }
        }
        __syncthreads();
        if (active) {
            for (int kk = 0; kk < nk; kk++) {
                unsigned ka = skb + kk*80u;
                unsigned va = svb + kk*80u;
                ull kv0, kv1, kv2, kv3, kv4, kv5, kv6, kv7;
                ull vv0, vv1, vv2, vv3, vv4, vv5, vv6, vv7;
                lds2(kv0, kv1, ka);       lds2(kv2, kv3, ka + 16u);
                lds2(kv4, kv5, ka + 32u); lds2(kv6, kv7, ka + 48u);
                lds2(vv0, vv1, va);       lds2(vv2, vv3, va + 16u);
                lds2(vv4, vv5, va + 32u); lds2(vv6, vv7, va + 48u);
#pragma unroll
                for (int p = 0; p < QPT; p++) {
                    ull a0 = fmul2(qq[p][0], kv0);
                    ull a1 = fmul2(qq[p][1], kv1);
                    a0 = ffma2(qq[p][2], kv2, a0);
                    a1 = ffma2(qq[p][3], kv3, a1);
                    a0 = ffma2(qq[p][4], kv4, a0);
                    a1 = ffma2(qq[p][5], kv5, a1);
                    a0 = ffma2(qq[p][6], kv6, a0);
                    a1 = ffma2(qq[p][7], kv7, a1);
                    a0 = fadd2(a0, a1);
                    float lo, hi; unpack2(a0, lo, hi);
                    float w = ex2(lo + hi);   // Q pre-scaled by log2(e)
                    l[p] += w;
                    ull wp = pack2(w, w);
                    oo[p][0] = ffma2(wp, vv0, oo[p][0]);
                    oo[p][1] = ffma2(wp, vv1, oo[p][1]);
                    oo[p][2] = ffma2(wp, vv2, oo[p][2]);
                    oo[p][3] = ffma2(wp, vv3, oo[p][3]);
                    oo[p][4] = ffma2(wp, vv4, oo[p][4]);
                    oo[p][5] = ffma2(wp, vv5, oo[p][5]);
                    oo[p][6] = ffma2(wp, vv6, oo[p][6]);
                    oo[p][7] = ffma2(wp, vv7, oo[p][7]);
                }
            }
        }
    }

#pragma unroll
    for (int p = 0; p < QPT; p++) {
        if (jj[p] < cnt) {
            int base = (ks*BH + bh)*T + jj[p];
            g_pL[base] = l[p];
            ull* op = (ull*)(g_pO + base*S);
#pragma unroll
            for (int i = 0; i < 8; i++) op[i] = oo[p][i];
        }
    }
}

// ------------------------------------------------------------------
// 4. Fused combine + projection, warp-per-row (high MLP gather).
//    Lane l owns 4 output floats; its 8 split partials are 8
//    independent LDG.128s. L reduced via 2 butterfly shuffles
//    within each 4-lane head group.
// ------------------------------------------------------------------
#define PRJ 8
__global__ __launch_bounds__(256) void proj_kernel(const float* __restrict__ bu,
                                                   float* __restrict__ out) {
    __shared__ float xs[PRJ][E];
    int b = blockIdx.y;
    int cnt = g_cnt[b];
    int rowbase = blockIdx.x * PRJ;
    if (rowbase >= cnt) return;
    int tid  = threadIdx.x;       // 256
    int warp = tid >> 5;          // 0..7: row within block
    int lane = tid & 31;
    int j = rowbase + warp;
    bool live = j < cnt;

    int h   = lane >> 2;          // head for this lane's 4 floats
    int off = (lane & 3) * 4;     // float offset within head
    int bh  = b*H + h;

    if (live) {
        // ---- gather: 8 independent float4 loads + 2 pL loads ----
        ull a0 = 0ULL, a1 = 0ULL;
        int ks2 = (lane & 3) * 2;      // this lane covers splits ks2, ks2+1
        float Lp = g_pL[(ks2*BH + bh)*T + j] + g_pL[((ks2+1)*BH + bh)*T + j];
#pragma unroll
        for (int ks = 0; ks < KSPLIT; ks++) {
            float4 v = *(const float4*)(g_pO + ((ks*BH + bh)*T + j)*S + off);
            a0 = fadd2(a0, pack2(v.x, v.y));
            a1 = fadd2(a1, pack2(v.z, v.w));
        }
        // reduce L across the 4-lane head group (lanes h*4..h*4+3)
        Lp += __shfl_xor_sync(0xffffffffu, Lp, 1);
        Lp += __shfl_xor_sync(0xffffffffu, Lp, 2);
        float invL = (Lp > 0.f) ? (1.0f / Lp) : 0.f;
        ull il2 = pack2(invL, invL);
        ull* xr = (ull*)&xs[warp][lane*4];
        xr[0] = fmul2(a0, il2);
        xr[1] = fmul2(a1, il2);
    }
    __syncthreads();

    // ---- GEMM: warp computes its row x Wu^T; lane = 4 cols ----
    if (live) {
        int cg = lane * 4;
        ull acc0 = 0ULL, acc1 = 0ULL;
#pragma unroll 8
        for (int i = 0; i < E; i++) {
            float xv = xs[warp][i];
            float4 w = *(const float4*)(g_WuT + i*E + cg);
            ull xp = pack2(xv, xv);
            acc0 = ffma2(xp, pack2(w.x, w.y), acc0);
            acc1 = ffma2(xp, pack2(w.z, w.w), acc1);
        }
        int t = g_idx[b*T + j];
        float4 bb = *(const float4*)(bu + cg);
        float o0, o1, o2, o3;
        unpack2(acc0, o0, o1);
        unpack2(acc1, o2, o3);
        *(float4*)(out + (b*T + t)*E + cg) =
            make_float4(o0 + bb.x, o1 + bb.y, o2 + bb.z, o3 + bb.w);
    }
}

// ------------------------------------------------------------------
extern "C" void kernel_launch(void* const* d_in, const int* in_sizes, int n_in,
                              void* d_out, int out_size) {
    const float* x     = (const float*)d_in[0];
    const int*   masks = (const int*)  d_in[1];
    const float* Wq    = (const float*)d_in[2];
    const float* Wk    = (const float*)d_in[3];
    const float* Wv    = (const float*)d_in[4];
    const float* Wu    = (const float*)d_in[5];
    const float* bu    = (const float*)d_in[6];
    float* out = (float*)d_out;

    prep_kernel<<<B + 16, 1024>>>(masks, Wu);
    qkv_kernel<<<(B*T*H)/256, 256>>>(x, masks, Wq, Wk, Wv, bu, out);
    attn_split_kernel<<<dim3(T/QBLK, BH, KSPLIT), ATH>>>();
    proj_kernel<<<dim3(T/PRJ, B), 256>>>(bu, out);
}